// round 5
// baseline (speedup 1.0000x reference)
#include <cuda_runtime.h>
#include <cstdint>

// FrozenBNBEmbedding: out[t, d] = code[ weight[input[t], d] ] * absmax[input[t]]
// DIM == BLOCK == 4096 -> absmax index == vocab row index.
//
// Inputs (metadata order):
//   d_in[0] = input  : int32 [4, 2048]       (8192 token ids)
//   d_in[1] = weight : int32 [50400, 4096]   (int8 codes as int32)
//   d_in[2] = absmax : float32 [50400]
//   d_in[3] = code   : float32 [256]
//   d_out   = float32 [4, 2048, 4096]
//
// Round-4: R1 skeleton (1 token per loop step, 256 thr, full occupancy)
// + 8-way bank-replicated LUT (8KB, conflict degree ~2 instead of ~4,
//   still 8 CTAs/SM)
// + persistent grid-stride over tokens (no wave tail, LUT init amortized)
// + streaming stores for the write-once output.

#define DIM      4096
#define NTOKENS  8192
#define THREADS  256
#define NSM      148
#define CTAS_PER_SM 8
#define NCTAS    (NSM * CTAS_PER_SM)   // 1184 persistent CTAs
#define LUT_REP  8

__global__ __launch_bounds__(THREADS, CTAS_PER_SM)
void bnb_embed_kernel(const int* __restrict__ input,
                      const int* __restrict__ weight,
                      const float* __restrict__ absmax,
                      const float* __restrict__ code,
                      float* __restrict__ out)
{
    // 8-way replicated LUT: word w holds code[w >> 3].
    // Lookup: s_lut[(byte << 3) + (lane & 7)].
    // Lane group c = lane&7 touches only banks {c, c+8, c+16, c+24}:
    // disjoint bank sets per group -> max conflict ~2 within 4-lane groups.
    __shared__ float s_lut[256 * LUT_REP];

    const int tid  = threadIdx.x;
    const int lane = tid & 31;

    #pragma unroll
    for (int w = tid; w < 256 * LUT_REP; w += THREADS)
        s_lut[w] = __ldg(&code[w >> 3]);   // coalesced STS, L1-hit LDG
    __syncthreads();

    const float* __restrict__ lut = s_lut + (lane & (LUT_REP - 1));

    // Persistent grid-stride over tokens.
    for (int t = blockIdx.x; t < NTOKENS; t += NCTAS) {
        const int tok = __ldg(&input[t]);
        const float scale = __ldg(&absmax[tok]);

        const int4* __restrict__ wrow =
            reinterpret_cast<const int4*>(weight + (size_t)tok * DIM);
        float4* __restrict__ orow =
            reinterpret_cast<float4*>(out + (size_t)t * DIM);

        // Front-batch all four 16B loads (MLP = 4 per thread).
        int4 q0 = wrow[tid];
        int4 q1 = wrow[tid + 256];
        int4 q2 = wrow[tid + 512];
        int4 q3 = wrow[tid + 768];

        float4 o;
        o.x = lut[(q0.x & 255) << 3] * scale;
        o.y = lut[(q0.y & 255) << 3] * scale;
        o.z = lut[(q0.z & 255) << 3] * scale;
        o.w = lut[(q0.w & 255) << 3] * scale;
        __stcs(&orow[tid], o);

        o.x = lut[(q1.x & 255) << 3] * scale;
        o.y = lut[(q1.y & 255) << 3] * scale;
        o.z = lut[(q1.z & 255) << 3] * scale;
        o.w = lut[(q1.w & 255) << 3] * scale;
        __stcs(&orow[tid + 256], o);

        o.x = lut[(q2.x & 255) << 3] * scale;
        o.y = lut[(q2.y & 255) << 3] * scale;
        o.z = lut[(q2.z & 255) << 3] * scale;
        o.w = lut[(q2.w & 255) << 3] * scale;
        __stcs(&orow[tid + 512], o);

        o.x = lut[(q3.x & 255) << 3] * scale;
        o.y = lut[(q3.y & 255) << 3] * scale;
        o.z = lut[(q3.z & 255) << 3] * scale;
        o.w = lut[(q3.w & 255) << 3] * scale;
        __stcs(&orow[tid + 768], o);
    }
}

extern "C" void kernel_launch(void* const* d_in, const int* in_sizes, int n_in,
                              void* d_out, int out_size)
{
    const int*   input  = (const int*)  d_in[0];
    const int*   weight = (const int*)  d_in[1];
    const float* absmax = (const float*)d_in[2];
    const float* code   = (const float*)d_in[3];
    float*       out    = (float*)d_out;

    bnb_embed_kernel<<<NCTAS, THREADS>>>(input, weight, absmax, code, out);
}

// round 6
// speedup vs baseline: 1.1125x; 1.1125x over previous
#include <cuda_runtime.h>
#include <cstdint>

// FrozenBNBEmbedding: out[t, d] = code[ weight[input[t], d] ] * absmax[input[t]]
// DIM == BLOCK == 4096 -> absmax index == vocab row index.
//
// Inputs (metadata order):
//   d_in[0] = input  : int32 [4, 2048]       (8192 token ids)
//   d_in[1] = weight : int32 [50400, 4096]   (int8 codes as int32)
//   d_in[2] = absmax : float32 [50400]
//   d_in[3] = code   : float32 [256]
//   d_out   = float32 [4, 2048, 4096]
//
// Round-5: R1 skeleton verbatim (CTA-per-token, grid=8192, plain stores,
// proven fastest) with ONE change: 16-way bank-replicated LUT (16KB).
//   lookup = s_lut[byte*16 + (lane&15)]
//   bank   = 16*(byte&1) + (lane&15)  -> only lane pairs (l, l+16) can
//   collide; expected conflict degree ~1.5 vs ~4.4 for the plain LUT.
// 8 CTAs x 16KB = 128KB smem/SM -> occupancy unchanged (8 CTAs, 64 warps).

#define DIM      4096
#define NTOKENS  8192
#define THREADS  256
#define LUT_REP  16

__global__ __launch_bounds__(THREADS, 8)
void bnb_embed_kernel(const int* __restrict__ input,
                      const int* __restrict__ weight,
                      const float* __restrict__ absmax,
                      const float* __restrict__ code,
                      float* __restrict__ out)
{
    __shared__ float s_lut[256 * LUT_REP];   // 16 KB

    const int tid  = threadIdx.x;
    const int lane = tid & 31;

    // Init: 4096 words / 256 threads = 16 coalesced STS per thread.
    // code[] is 1KB -> L1/L2 resident after the first CTAs.
    #pragma unroll
    for (int w = tid; w < 256 * LUT_REP; w += THREADS)
        s_lut[w] = __ldg(&code[w >> 4]);
    __syncthreads();

    const float* __restrict__ lut = s_lut + (lane & (LUT_REP - 1));

    const int t   = blockIdx.x;              // token index 0..8191
    const int tok = input[t];                // vocab row (CTA-startup chase)
    const float scale = __ldg(&absmax[tok]);

    const int4* __restrict__ wrow =
        reinterpret_cast<const int4*>(weight + (size_t)tok * DIM);
    float4* __restrict__ orow =
        reinterpret_cast<float4*>(out + (size_t)t * DIM);

    // Front-batch all four 16B loads (MLP=4 per thread).
    int4 q0 = wrow[tid];
    int4 q1 = wrow[tid + 256];
    int4 q2 = wrow[tid + 512];
    int4 q3 = wrow[tid + 768];

    float4 o;
    o.x = lut[(q0.x & 255) << 4] * scale;
    o.y = lut[(q0.y & 255) << 4] * scale;
    o.z = lut[(q0.z & 255) << 4] * scale;
    o.w = lut[(q0.w & 255) << 4] * scale;
    orow[tid] = o;

    o.x = lut[(q1.x & 255) << 4] * scale;
    o.y = lut[(q1.y & 255) << 4] * scale;
    o.z = lut[(q1.z & 255) << 4] * scale;
    o.w = lut[(q1.w & 255) << 4] * scale;
    orow[tid + 256] = o;

    o.x = lut[(q2.x & 255) << 4] * scale;
    o.y = lut[(q2.y & 255) << 4] * scale;
    o.z = lut[(q2.z & 255) << 4] * scale;
    o.w = lut[(q2.w & 255) << 4] * scale;
    orow[tid + 512] = o;

    o.x = lut[(q3.x & 255) << 4] * scale;
    o.y = lut[(q3.y & 255) << 4] * scale;
    o.z = lut[(q3.z & 255) << 4] * scale;
    o.w = lut[(q3.w & 255) << 4] * scale;
    orow[tid + 768] = o;
}

extern "C" void kernel_launch(void* const* d_in, const int* in_sizes, int n_in,
                              void* d_out, int out_size)
{
    const int*   input  = (const int*)  d_in[0];
    const int*   weight = (const int*)  d_in[1];
    const float* absmax = (const float*)d_in[2];
    const float* code   = (const float*)d_in[3];
    float*       out    = (float*)d_out;

    bnb_embed_kernel<<<NTOKENS, THREADS>>>(input, weight, absmax, code, out);
}

// round 7
// speedup vs baseline: 1.1258x; 1.0119x over previous
#include <cuda_runtime.h>
#include <cstdint>

// FrozenBNBEmbedding: out[t, d] = code[ weight[input[t], d] ] * absmax[input[t]]
// DIM == BLOCK == 4096 -> absmax index == vocab row index.
//
// Inputs (metadata order):
//   d_in[0] = input  : int32 [4, 2048]       (8192 token ids)
//   d_in[1] = weight : int32 [50400, 4096]   (int8 codes as int32)
//   d_in[2] = absmax : float32 [50400]
//   d_in[3] = code   : float32 [256]
//   d_out   = float32 [4, 2048, 4096]
//
// Round-6: 1024-thread CTA = FOUR parallel 256-thread slices, each slice
// doing R1's one-token job (no serial token loop, no extra regs), sharing
// ONE 16-way bank-replicated LUT (16KB):
//   - init amortized to 4 STS/thread over 4 tokens (12.5% overhead)
//   - lookup conflict degree ~1.5 (bank = 16*(byte&1) + (lane&15))
//   - occupancy: 2 CTAs/SM x 1024 thr = 64 warps (same as R1)

#define DIM      4096
#define NTOKENS  8192
#define THREADS  1024
#define T_PER_CTA 4
#define NCTAS    (NTOKENS / T_PER_CTA)   // 2048
#define LUT_REP  16

__global__ __launch_bounds__(THREADS, 2)
void bnb_embed_kernel(const int* __restrict__ input,
                      const int* __restrict__ weight,
                      const float* __restrict__ absmax,
                      const float* __restrict__ code,
                      float* __restrict__ out)
{
    __shared__ float s_lut[256 * LUT_REP];   // 16 KB, shared by 4 slices

    const int tid  = threadIdx.x;
    const int lane = tid & 31;

    // Init: 4096 words / 1024 threads = 4 coalesced STS per thread.
    #pragma unroll
    for (int w = tid; w < 256 * LUT_REP; w += THREADS)
        s_lut[w] = __ldg(&code[w >> 4]);
    __syncthreads();

    const float* __restrict__ lut = s_lut + (lane & (LUT_REP - 1));

    // Slice s (0..3) handles token blockIdx.x*4 + s, exactly like an R1 CTA.
    const int slice = tid >> 8;        // 0..3
    const int i     = tid & 255;       // 0..255 within slice
    const int t     = blockIdx.x * T_PER_CTA + slice;

    const int tok = __ldg(&input[t]);
    const float scale = __ldg(&absmax[tok]);

    const int4* __restrict__ wrow =
        reinterpret_cast<const int4*>(weight + (size_t)tok * DIM);
    float4* __restrict__ orow =
        reinterpret_cast<float4*>(out + (size_t)t * DIM);

    // Front-batch all four 16B loads (MLP = 4 per thread).
    int4 q0 = wrow[i];
    int4 q1 = wrow[i + 256];
    int4 q2 = wrow[i + 512];
    int4 q3 = wrow[i + 768];

    float4 o;
    o.x = lut[(q0.x & 255) << 4] * scale;
    o.y = lut[(q0.y & 255) << 4] * scale;
    o.z = lut[(q0.z & 255) << 4] * scale;
    o.w = lut[(q0.w & 255) << 4] * scale;
    orow[i] = o;

    o.x = lut[(q1.x & 255) << 4] * scale;
    o.y = lut[(q1.y & 255) << 4] * scale;
    o.z = lut[(q1.z & 255) << 4] * scale;
    o.w = lut[(q1.w & 255) << 4] * scale;
    orow[i + 256] = o;

    o.x = lut[(q2.x & 255) << 4] * scale;
    o.y = lut[(q2.y & 255) << 4] * scale;
    o.z = lut[(q2.z & 255) << 4] * scale;
    o.w = lut[(q2.w & 255) << 4] * scale;
    orow[i + 512] = o;

    o.x = lut[(q3.x & 255) << 4] * scale;
    o.y = lut[(q3.y & 255) << 4] * scale;
    o.z = lut[(q3.z & 255) << 4] * scale;
    o.w = lut[(q3.w & 255) << 4] * scale;
    orow[i + 768] = o;
}

extern "C" void kernel_launch(void* const* d_in, const int* in_sizes, int n_in,
                              void* d_out, int out_size)
{
    const int*   input  = (const int*)  d_in[0];
    const int*   weight = (const int*)  d_in[1];
    const float* absmax = (const float*)d_in[2];
    const float* code   = (const float*)d_in[3];
    float*       out    = (float*)d_out;

    bnb_embed_kernel<<<NCTAS, THREADS>>>(input, weight, absmax, code, out);
}